// round 6
// baseline (speedup 1.0000x reference)
#include <cuda_runtime.h>
#include <cuda_bf16.h>
#include <math.h>
#include <stdint.h>

#define B_      16
#define CIN_    256
#define COUT_   256
#define HW_     64
#define KN_     4
#define PI_F    3.14159265358979323846f
#define BN_EPS_ 1e-5f

#define PADW    66
#define PROWS   (PADW * PADW)

// ---------------- scratch (static __device__, no allocation) ----------------
__device__ float g_pooled[B_ * CIN_];
__device__ float g_T[B_ * 9 * 36];
__device__ __nv_bfloat16 g_wh[(size_t)B_ * 9 * COUT_ * CIN_];   // [b][k][co][ci] hi
__device__ __nv_bfloat16 g_wl[(size_t)B_ * 9 * COUT_ * CIN_];   // lo
__device__ __nv_bfloat16 g_xh[(size_t)B_ * PROWS * CIN_];       // [b][padded px][ci] hi
__device__ __nv_bfloat16 g_xl[(size_t)B_ * PROWS * CIN_];       // lo

// ---------------- helpers ----------------
__device__ __forceinline__ uint32_t smem_u32(const void* p) {
    uint32_t a;
    asm("{ .reg .u64 t; cvta.to.shared.u64 t, %1; cvt.u32.u64 %0, t; }" : "=r"(a) : "l"(p));
    return a;
}
#define SWZ128(o) ((o) ^ (((o) >> 3) & 0x70))

#define CP_ASYNC16(dst, src) asm volatile("cp.async.cg.shared.global [%0], [%1], 16;" :: "r"(dst), "l"(src) : "memory")
#define CP_COMMIT()          asm volatile("cp.async.commit_group;" ::: "memory")

#define LDSM_X4(r, a)                                                                     \
    asm volatile("ldmatrix.sync.aligned.m8n8.x4.shared.b16 {%0,%1,%2,%3}, [%4];"          \
                 : "=r"((r)[0]), "=r"((r)[1]), "=r"((r)[2]), "=r"((r)[3]) : "r"(a))

#define MMA_BF16(d, a, b0, b1)                                                            \
    asm volatile("mma.sync.aligned.m16n8k16.row.col.f32.bf16.bf16.f32 "                   \
                 "{%0,%1,%2,%3},{%4,%5,%6,%7},{%8,%9},{%0,%1,%2,%3};"                     \
                 : "+f"((d)[0]), "+f"((d)[1]), "+f"((d)[2]), "+f"((d)[3])                 \
                 : "r"((a)[0]), "r"((a)[1]), "r"((a)[2]), "r"((a)[3]), "r"(b0), "r"(b1))

// ---------------- kernel 1: global average pool ----------------
__global__ void pool_kernel(const float* __restrict__ x) {
    int blk = blockIdx.x;
    const float* p = x + (size_t)blk * (HW_ * HW_);
    float s = 0.f;
    for (int i = threadIdx.x; i < HW_ * HW_; i += 256) s += p[i];
    #pragma unroll
    for (int o = 16; o; o >>= 1) s += __shfl_xor_sync(0xffffffffu, s, o);
    __shared__ float red[8];
    if ((threadIdx.x & 31) == 0) red[threadIdx.x >> 5] = s;
    __syncthreads();
    if (threadIdx.x == 0) {
        float t = 0.f;
        #pragma unroll
        for (int i = 0; i < 8; i++) t += red[i];
        g_pooled[blk] = t * (1.f / (HW_ * HW_));
    }
}

// ---------------- kernel 2: routing heads + rotation matrices -> g_T ----------------
__global__ void route_kernel(const float* __restrict__ wl, const float* __restrict__ wt) {
    int t = threadIdx.x;
    if (t >= B_ * KN_) return;
    int b = t >> 2, n = t & 3;
    const float* p = g_pooled + b * CIN_;
    float dl = 0.f, dt = 0.f;
    for (int c = 0; c < CIN_; c++) {
        float pc = p[c];
        dl += pc * wl[c * KN_ + n];
        dt += pc * wt[c * KN_ + n];
    }
    float lam = 1.f / (1.f + expf(-dl));
    float th  = (dt / (1.f + fabsf(dt))) * PI_F;

    float xc = cosf(th), ys = sinf(th);
    float a = xc - ys, bxy = xc * ys, cc = xc + ys;

    float R[81];
    #pragma unroll
    for (int i = 0; i < 81; i++) R[i] = 0.f;

    if (th >= 0.f) {
        R[0]  = a;          R[1]  = 1.f - a;
        R[10] = xc - bxy;   R[11] = bxy;        R[13] = 1.f - cc + bxy; R[14] = ys - bxy;
        R[20] = a;          R[23] = 1.f - a;
        R[27] = bxy;        R[28] = ys - bxy;   R[30] = xc - bxy;       R[31] = 1.f - cc + bxy;
        R[40] = 1.f;
        R[49] = 1.f - cc + bxy; R[50] = xc - bxy; R[52] = ys - bxy;     R[53] = bxy;
        R[57] = 1.f - a;    R[60] = a;
        R[66] = ys - bxy;   R[67] = 1.f - cc + bxy; R[69] = bxy;        R[70] = xc - bxy;
        R[79] = 1.f - a;    R[80] = a;
    } else {
        R[0]  = cc;         R[3]  = 1.f - cc;
        R[9]  = -bxy;       R[10] = xc + bxy;   R[12] = bxy - ys;       R[13] = 1.f - a - bxy;
        R[19] = 1.f - cc;   R[20] = cc;
        R[30] = xc + bxy;   R[31] = 1.f - a - bxy; R[33] = -bxy;        R[34] = bxy - ys;
        R[40] = 1.f;
        R[46] = bxy - ys;   R[47] = -bxy;       R[49] = 1.f - a - bxy;  R[50] = xc + bxy;
        R[60] = cc;         R[61] = 1.f - cc;
        R[67] = 1.f - a - bxy; R[68] = bxy - ys; R[70] = xc + bxy;      R[71] = -bxy;
        R[77] = 1.f - cc;   R[80] = cc;
    }

    #pragma unroll
    for (int pp = 0; pp < 9; pp++)
        #pragma unroll
        for (int q = 0; q < 9; q++)
            g_T[b * 324 + pp * 36 + n * 9 + q] = lam * R[pp * 9 + q];
}

// ---------------- kernel 3: rotated weights -> bf16 hi/lo [b][k][co][ci] ----------------
// smem-staged coalesced weight reads.
__global__ void rotw_kernel(const float* __restrict__ weight) {
    int co = blockIdx.x;
    int b  = blockIdx.y;
    int ci = threadIdx.x;
    int tid = threadIdx.x;

    __shared__ float T[324];
    __shared__ float ws[CIN_ * 9];          // 9 KB, per-n slice

    for (int i = tid; i < 324; i += 256) T[i] = g_T[b * 324 + i];

    float wv[36];
    #pragma unroll
    for (int n = 0; n < KN_; n++) {
        const float* wp = weight + ((size_t)(n * COUT_ + co)) * CIN_ * 9;
        __syncthreads();
        for (int i = tid; i < CIN_ * 9; i += 256) ws[i] = wp[i];
        __syncthreads();
        #pragma unroll
        for (int q = 0; q < 9; q++) wv[n * 9 + q] = ws[ci * 9 + q];
    }

    #pragma unroll
    for (int p = 0; p < 9; p++) {
        float s = 0.f;
        #pragma unroll
        for (int m = 0; m < 36; m++) s += T[p * 36 + m] * wv[m];
        __nv_bfloat16 hi = __float2bfloat16(s);
        __nv_bfloat16 lo = __float2bfloat16(s - __bfloat162float(hi));
        size_t o = ((size_t)(b * 9 + p) * COUT_ + co) * CIN_ + ci;
        g_wh[o] = hi;
        g_wl[o] = lo;
    }
}

// ---------------- kernel 4: zero padded borders (only 260 rows/batch) ----------------
__global__ void border_kernel() {
    int r = blockIdx.x;
    int b = blockIdx.y;
    int pr;
    if (r < 66)       pr = r;                                // top row
    else if (r < 132) pr = PROWS - 66 + (r - 66);            // bottom row
    else if (r < 196) pr = (r - 131) * PADW;                 // left col rows 1..64
    else              pr = (r - 195) * PADW + 65;            // right col rows 1..64
    size_t base = ((size_t)b * PROWS + pr) * CIN_;
    int t = threadIdx.x;
    ((uint32_t*)(g_xh + base))[t] = 0u;
    ((uint32_t*)(g_xl + base))[t] = 0u;
}

// ---------------- kernel 5: transpose+convert x -> xT[b][padded px][ci] hi/lo ----------------
__global__ void xpose_kernel(const float* __restrict__ x) {
    int b   = blockIdx.z;
    int ci0 = blockIdx.y * 64;
    int px0 = blockIdx.x * 32;
    __shared__ float t[64][33];
    int tx = threadIdx.x & 31, ty = threadIdx.x >> 5;

    const float* xb = x + ((size_t)(b * CIN_ + ci0)) * (HW_ * HW_) + px0;
    #pragma unroll
    for (int i = 0; i < 8; i++)
        t[ty + 8 * i][tx] = xb[(size_t)(ty + 8 * i) * (HW_ * HW_) + tx];
    __syncthreads();

    #pragma unroll
    for (int i = 0; i < 4; i++) {
        int px = px0 + ty + 8 * i;
        int h = px >> 6, w = px & 63;
        int pr = (h + 1) * PADW + (w + 1);
        size_t base = ((size_t)b * PROWS + pr) * CIN_ + ci0;
        float a0 = t[2 * tx][ty + 8 * i];
        float a1 = t[2 * tx + 1][ty + 8 * i];
        __nv_bfloat16 h0 = __float2bfloat16(a0);
        __nv_bfloat16 h1 = __float2bfloat16(a1);
        __nv_bfloat16 l0 = __float2bfloat16(a0 - __bfloat162float(h0));
        __nv_bfloat16 l1 = __float2bfloat16(a1 - __bfloat162float(h1));
        __nv_bfloat162 vh; vh.x = h0; vh.y = h1;
        __nv_bfloat162 vl; vl.x = l0; vl.y = l1;
        ((__nv_bfloat162*)(g_xh + base))[tx] = vh;
        ((__nv_bfloat162*)(g_xl + base))[tx] = vl;
    }
}

// ---------------- kernel 6: HMMA conv GEMM + BN + ReLU ----------------
// CTA tile 128 co x 128 px; 8 warps (2m x 4n), warp tile 64 co x 32 px.
// 36 stages (9 taps x 4 ci-chunks of 64), 64KB/stage, triple buffered.
#define BUF_BYTES 65536
#define NSTAGE    36

__device__ __forceinline__ void stage_tiles(uint32_t buf, int b, int cog, int pxg,
                                            int s, int tid) {
    int k   = s >> 2;
    int ci0 = (s & 3) << 6;
    int dh  = k / 3 - 1, dw = k % 3 - 1;

    // A: weights [128 co x 64 ci] hi+lo = 2048 x 16B
    size_t wbase = (((size_t)(b * 9 + k) * COUT_ + cog * 128) * CIN_ + ci0) * 2;
    #pragma unroll
    for (int it = 0; it < 8; it++) {
        int c = tid + it * 256;
        int row = c >> 3, c16 = c & 7;
        int hl = row >> 7, r = row & 127;
        uint32_t dst = buf + (uint32_t)hl * 16384 + SWZ128((uint32_t)(r * 128 + c16 * 16));
        const char* src = (const char*)(hl ? g_wl : g_wh) + wbase + (size_t)r * 512 + c16 * 16;
        CP_ASYNC16(dst, src);
    }
    // B: x rows [128 px x 64 ci] hi+lo = 2048 x 16B
    int hbase = 2 * pxg + dh + 1;
    #pragma unroll
    for (int it = 0; it < 8; it++) {
        int c = tid + it * 256;
        int row = c >> 3, c16 = c & 7;
        int hl = row >> 7, p = row & 127;
        int hh = p >> 6, ww = p & 63;
        int pr = (hbase + hh) * PADW + (ww + dw + 1);
        uint32_t dst = buf + 32768 + (uint32_t)hl * 16384 + SWZ128((uint32_t)(p * 128 + c16 * 16));
        const char* src = (const char*)(hl ? g_xl : g_xh)
                          + (((size_t)b * PROWS + pr) * CIN_ + ci0) * 2 + c16 * 16;
        CP_ASYNC16(dst, src);
    }
}

__global__ void __launch_bounds__(256, 1)
conv_kernel(const float* __restrict__ bn_gamma, const float* __restrict__ bn_beta,
            const float* __restrict__ bn_mean,  const float* __restrict__ bn_var,
            float* __restrict__ out) {
    extern __shared__ char smem[];
    uint32_t sbase = smem_u32(smem);
    int b   = blockIdx.z;
    int cog = blockIdx.y;
    int pxg = blockIdx.x;
    int tid = threadIdx.x;
    int wid = tid >> 5;
    int lane = tid & 31;
    int warp_m = wid >> 2;          // 0..1 -> 64 co
    int warp_n = wid & 3;           // 0..3 -> 32 px

    float acc[4][4][4];
    #pragma unroll
    for (int i = 0; i < 4; i++)
        #pragma unroll
        for (int j = 0; j < 4; j++)
            #pragma unroll
            for (int r = 0; r < 4; r++) acc[i][j][r] = 0.f;

    int lA_row = lane & 15;
    int lA_k16 = lane >> 4;
    int lB_row = (lane & 7) + ((lane >> 4) & 1) * 8;
    int lB_k16 = (lane >> 3) & 1;

    uint32_t bufs[3] = { sbase + 1024, sbase + 1024 + BUF_BYTES, sbase + 1024 + 2 * BUF_BYTES };

    stage_tiles(bufs[0], b, cog, pxg, 0, tid); CP_COMMIT();
    stage_tiles(bufs[1], b, cog, pxg, 1, tid); CP_COMMIT();
    stage_tiles(bufs[2], b, cog, pxg, 2, tid); CP_COMMIT();

    int idx = 0;
    for (int s = 0; s < NSTAGE; s++) {
        if (s + 3 < NSTAGE)      asm volatile("cp.async.wait_group 2;" ::: "memory");
        else if (s + 2 < NSTAGE) asm volatile("cp.async.wait_group 1;" ::: "memory");
        else                     asm volatile("cp.async.wait_group 0;" ::: "memory");
        __syncthreads();

        uint32_t buf = bufs[idx];
        uint32_t Ah = buf, Al = buf + 16384, Bh = buf + 32768, Bl = buf + 49152;

        #pragma unroll
        for (int kf = 0; kf < 4; kf++) {
            uint32_t ah[16], a2[16], bb[8];
            uint32_t offA[4], offB[2];
            #pragma unroll
            for (int mi = 0; mi < 4; mi++) {
                offA[mi] = SWZ128((uint32_t)((warp_m * 64 + mi * 16 + lA_row) * 128
                                             + kf * 32 + lA_k16 * 16));
                LDSM_X4(&ah[mi * 4], Ah + offA[mi]);
            }
            #pragma unroll
            for (int j = 0; j < 2; j++) {
                offB[j] = SWZ128((uint32_t)((warp_n * 32 + j * 16 + lB_row) * 128
                                            + kf * 32 + lB_k16 * 16));
                LDSM_X4(&bb[j * 4], Bh + offB[j]);
            }
            // pass 1: Ah * Bh
            #pragma unroll
            for (int mi = 0; mi < 4; mi++)
                #pragma unroll
                for (int ni = 0; ni < 4; ni++)
                    MMA_BF16(acc[mi][ni], &ah[mi * 4],
                             bb[(ni >> 1) * 4 + (ni & 1) * 2], bb[(ni >> 1) * 4 + (ni & 1) * 2 + 1]);
            // pass 2: Al * Bh
            #pragma unroll
            for (int mi = 0; mi < 4; mi++) LDSM_X4(&a2[mi * 4], Al + offA[mi]);
            #pragma unroll
            for (int mi = 0; mi < 4; mi++)
                #pragma unroll
                for (int ni = 0; ni < 4; ni++)
                    MMA_BF16(acc[mi][ni], &a2[mi * 4],
                             bb[(ni >> 1) * 4 + (ni & 1) * 2], bb[(ni >> 1) * 4 + (ni & 1) * 2 + 1]);
            // pass 3: Ah * Bl
            #pragma unroll
            for (int j = 0; j < 2; j++) LDSM_X4(&bb[j * 4], Bl + offB[j]);
            #pragma unroll
            for (int mi = 0; mi < 4; mi++)
                #pragma unroll
                for (int ni = 0; ni < 4; ni++)
                    MMA_BF16(acc[mi][ni], &ah[mi * 4],
                             bb[(ni >> 1) * 4 + (ni & 1) * 2], bb[(ni >> 1) * 4 + (ni & 1) * 2 + 1]);
        }

        __syncthreads();
        if (s + 3 < NSTAGE) { stage_tiles(bufs[idx], b, cog, pxg, s + 3, tid); CP_COMMIT(); }
        idx = (idx == 2) ? 0 : idx + 1;
    }

    // ---------------- epilogue: BN + ReLU + store ----------------
    int co0 = cog * 128 + warp_m * 64;
    float sc[8], sb[8];
    #pragma unroll
    for (int mi = 0; mi < 4; mi++)
        #pragma unroll
        for (int h = 0; h < 2; h++) {
            int co = co0 + mi * 16 + (lane >> 2) + h * 8;
            float s = bn_gamma[co] * rsqrtf(bn_var[co] + BN_EPS_);
            sc[mi * 2 + h] = s;
            sb[mi * 2 + h] = bn_beta[co] - bn_mean[co] * s;
        }

    int pxbase = pxg * 128 + warp_n * 32 + (lane & 3) * 2;
    #pragma unroll
    for (int mi = 0; mi < 4; mi++)
        #pragma unroll
        for (int h = 0; h < 2; h++) {
            int co = co0 + mi * 16 + (lane >> 2) + h * 8;
            float s = sc[mi * 2 + h], bbn = sb[mi * 2 + h];
            float* op = out + ((size_t)(b * COUT_ + co)) * (HW_ * HW_);
            #pragma unroll
            for (int ni = 0; ni < 4; ni++) {
                float2 v;
                v.x = fmaxf(acc[mi][ni][h * 2 + 0] * s + bbn, 0.f);
                v.y = fmaxf(acc[mi][ni][h * 2 + 1] * s + bbn, 0.f);
                *(float2*)(op + pxbase + ni * 8) = v;
            }
        }
}

// ---------------- launcher ----------------
extern "C" void kernel_launch(void* const* d_in, const int* in_sizes, int n_in,
                              void* d_out, int out_size) {
    const float* x        = (const float*)d_in[0];
    const float* weight   = (const float*)d_in[1];
    const float* w_lambda = (const float*)d_in[2];
    const float* w_theta  = (const float*)d_in[3];
    const float* bn_gamma = (const float*)d_in[4];
    const float* bn_beta  = (const float*)d_in[5];
    const float* bn_mean  = (const float*)d_in[6];
    const float* bn_var   = (const float*)d_in[7];
    float* out = (float*)d_out;

    cudaFuncSetAttribute(conv_kernel, cudaFuncAttributeMaxDynamicSharedMemorySize,
                         1024 + 3 * BUF_BYTES);

    pool_kernel<<<B_ * CIN_, 256>>>(x);
    route_kernel<<<1, 64>>>(w_lambda, w_theta);
    rotw_kernel<<<dim3(COUT_, B_), 256>>>(weight);
    border_kernel<<<dim3(260, B_), 128>>>();
    xpose_kernel<<<dim3(128, 4, B_), 256>>>(x);
    conv_kernel<<<dim3(32, 2, B_), 256, 1024 + 3 * BUF_BYTES>>>(
        bn_gamma, bn_beta, bn_mean, bn_var, out);
}

// round 10
// speedup vs baseline: 1.4356x; 1.4356x over previous
#include <cuda_runtime.h>
#include <cuda_bf16.h>
#include <math.h>
#include <stdint.h>

#define B_      16
#define CIN_    256
#define COUT_   256
#define HW_     64
#define KN_     4
#define PI_F    3.14159265358979323846f
#define BN_EPS_ 1e-5f

#define PADW    66
#define PROWS   (PADW * PADW)

// ---------------- scratch (static __device__, no allocation) ----------------
__device__ float g_pooled[B_ * CIN_];
__device__ float g_T[B_ * 9 * 36];
__device__ __nv_bfloat16 g_wh[(size_t)B_ * 9 * COUT_ * CIN_];   // [b][k][co][ci] hi
__device__ __nv_bfloat16 g_wl[(size_t)B_ * 9 * COUT_ * CIN_];   // lo
__device__ __nv_bfloat16 g_xh[(size_t)B_ * PROWS * CIN_];       // [b][padded px][ci] hi
__device__ __nv_bfloat16 g_xl[(size_t)B_ * PROWS * CIN_];       // lo

// ---------------- helpers ----------------
__device__ __forceinline__ uint32_t smem_u32(const void* p) {
    uint32_t a;
    asm("{ .reg .u64 t; cvta.to.shared.u64 t, %1; cvt.u32.u64 %0, t; }" : "=r"(a) : "l"(p));
    return a;
}
#define SWZ128(o) ((o) ^ (((o) >> 3) & 0x70))

#define CP_ASYNC16(dst, src) asm volatile("cp.async.cg.shared.global [%0], [%1], 16;" :: "r"(dst), "l"(src) : "memory")
#define CP_COMMIT()          asm volatile("cp.async.commit_group;" ::: "memory")

#define LDSM_X4(r, a)                                                                     \
    asm volatile("ldmatrix.sync.aligned.m8n8.x4.shared.b16 {%0,%1,%2,%3}, [%4];"          \
                 : "=r"((r)[0]), "=r"((r)[1]), "=r"((r)[2]), "=r"((r)[3]) : "r"(a))

#define MMA_BF16(d, a, b0, b1)                                                            \
    asm volatile("mma.sync.aligned.m16n8k16.row.col.f32.bf16.bf16.f32 "                   \
                 "{%0,%1,%2,%3},{%4,%5,%6,%7},{%8,%9},{%0,%1,%2,%3};"                     \
                 : "+f"((d)[0]), "+f"((d)[1]), "+f"((d)[2]), "+f"((d)[3])                 \
                 : "r"((a)[0]), "r"((a)[1]), "r"((a)[2]), "r"((a)[3]), "r"(b0), "r"(b1))

// ---------------- kernel 1: global average pool ----------------
__global__ void pool_kernel(const float* __restrict__ x) {
    int blk = blockIdx.x;
    const float* p = x + (size_t)blk * (HW_ * HW_);
    float s = 0.f;
    for (int i = threadIdx.x; i < HW_ * HW_; i += 256) s += p[i];
    #pragma unroll
    for (int o = 16; o; o >>= 1) s += __shfl_xor_sync(0xffffffffu, s, o);
    __shared__ float red[8];
    if ((threadIdx.x & 31) == 0) red[threadIdx.x >> 5] = s;
    __syncthreads();
    if (threadIdx.x == 0) {
        float t = 0.f;
        #pragma unroll
        for (int i = 0; i < 8; i++) t += red[i];
        g_pooled[blk] = t * (1.f / (HW_ * HW_));
    }
}

// ---------------- kernel 2: routing heads + rotation matrices -> g_T ----------------
__global__ void route_kernel(const float* __restrict__ wl, const float* __restrict__ wt) {
    int t = threadIdx.x;
    if (t >= B_ * KN_) return;
    int b = t >> 2, n = t & 3;
    const float* p = g_pooled + b * CIN_;
    float dl = 0.f, dt = 0.f;
    for (int c = 0; c < CIN_; c++) {
        float pc = p[c];
        dl += pc * wl[c * KN_ + n];
        dt += pc * wt[c * KN_ + n];
    }
    float lam = 1.f / (1.f + expf(-dl));
    float th  = (dt / (1.f + fabsf(dt))) * PI_F;

    float xc = cosf(th), ys = sinf(th);
    float a = xc - ys, bxy = xc * ys, cc = xc + ys;

    float R[81];
    #pragma unroll
    for (int i = 0; i < 81; i++) R[i] = 0.f;

    if (th >= 0.f) {
        R[0]  = a;          R[1]  = 1.f - a;
        R[10] = xc - bxy;   R[11] = bxy;        R[13] = 1.f - cc + bxy; R[14] = ys - bxy;
        R[20] = a;          R[23] = 1.f - a;
        R[27] = bxy;        R[28] = ys - bxy;   R[30] = xc - bxy;       R[31] = 1.f - cc + bxy;
        R[40] = 1.f;
        R[49] = 1.f - cc + bxy; R[50] = xc - bxy; R[52] = ys - bxy;     R[53] = bxy;
        R[57] = 1.f - a;    R[60] = a;
        R[66] = ys - bxy;   R[67] = 1.f - cc + bxy; R[69] = bxy;        R[70] = xc - bxy;
        R[79] = 1.f - a;    R[80] = a;
    } else {
        R[0]  = cc;         R[3]  = 1.f - cc;
        R[9]  = -bxy;       R[10] = xc + bxy;   R[12] = bxy - ys;       R[13] = 1.f - a - bxy;
        R[19] = 1.f - cc;   R[20] = cc;
        R[30] = xc + bxy;   R[31] = 1.f - a - bxy; R[33] = -bxy;        R[34] = bxy - ys;
        R[40] = 1.f;
        R[46] = bxy - ys;   R[47] = -bxy;       R[49] = 1.f - a - bxy;  R[50] = xc + bxy;
        R[60] = cc;         R[61] = 1.f - cc;
        R[67] = 1.f - a - bxy; R[68] = bxy - ys; R[70] = xc + bxy;      R[71] = -bxy;
        R[77] = 1.f - cc;   R[80] = cc;
    }

    #pragma unroll
    for (int pp = 0; pp < 9; pp++)
        #pragma unroll
        for (int q = 0; q < 9; q++)
            g_T[b * 324 + pp * 36 + n * 9 + q] = lam * R[pp * 9 + q];
}

// ---------------- kernel 3: rotated weights -> bf16 hi/lo [b][k][co][ci] ----------------
// smem-staged coalesced weight reads (verified in R6).
__global__ void rotw_kernel(const float* __restrict__ weight) {
    int co = blockIdx.x;
    int b  = blockIdx.y;
    int ci = threadIdx.x;
    int tid = threadIdx.x;

    __shared__ float T[324];
    __shared__ float ws[CIN_ * 9];          // 9 KB, per-n slice

    for (int i = tid; i < 324; i += 256) T[i] = g_T[b * 324 + i];

    float wv[36];
    #pragma unroll
    for (int n = 0; n < KN_; n++) {
        const float* wp = weight + ((size_t)(n * COUT_ + co)) * CIN_ * 9;
        __syncthreads();
        for (int i = tid; i < CIN_ * 9; i += 256) ws[i] = wp[i];
        __syncthreads();
        #pragma unroll
        for (int q = 0; q < 9; q++) wv[n * 9 + q] = ws[ci * 9 + q];
    }

    #pragma unroll
    for (int p = 0; p < 9; p++) {
        float s = 0.f;
        #pragma unroll
        for (int m = 0; m < 36; m++) s += T[p * 36 + m] * wv[m];
        __nv_bfloat16 hi = __float2bfloat16(s);
        __nv_bfloat16 lo = __float2bfloat16(s - __bfloat162float(hi));
        size_t o = ((size_t)(b * 9 + p) * COUT_ + co) * CIN_ + ci;
        g_wh[o] = hi;
        g_wl[o] = lo;
    }
}

// ---------------- kernel 4: zero padded borders (only 260 rows/batch; verified in R6) ----
__global__ void border_kernel() {
    int r = blockIdx.x;
    int b = blockIdx.y;
    int pr;
    if (r < 66)       pr = r;                                // top row
    else if (r < 132) pr = PROWS - 66 + (r - 66);            // bottom row
    else if (r < 196) pr = (r - 131) * PADW;                 // left col rows 1..64
    else              pr = (r - 195) * PADW + 65;            // right col rows 1..64
    size_t base = ((size_t)b * PROWS + pr) * CIN_;
    int t = threadIdx.x;
    ((uint32_t*)(g_xh + base))[t] = 0u;
    ((uint32_t*)(g_xl + base))[t] = 0u;
}

// ---------------- kernel 5: transpose+convert x -> xT[b][padded px][ci] hi/lo ----------------
__global__ void xpose_kernel(const float* __restrict__ x) {
    int b   = blockIdx.z;
    int ci0 = blockIdx.y * 64;
    int px0 = blockIdx.x * 32;
    __shared__ float t[64][33];
    int tx = threadIdx.x & 31, ty = threadIdx.x >> 5;

    const float* xb = x + ((size_t)(b * CIN_ + ci0)) * (HW_ * HW_) + px0;
    #pragma unroll
    for (int i = 0; i < 8; i++)
        t[ty + 8 * i][tx] = xb[(size_t)(ty + 8 * i) * (HW_ * HW_) + tx];
    __syncthreads();

    #pragma unroll
    for (int i = 0; i < 4; i++) {
        int px = px0 + ty + 8 * i;
        int h = px >> 6, w = px & 63;
        int pr = (h + 1) * PADW + (w + 1);
        size_t base = ((size_t)b * PROWS + pr) * CIN_ + ci0;
        float a0 = t[2 * tx][ty + 8 * i];
        float a1 = t[2 * tx + 1][ty + 8 * i];
        __nv_bfloat16 h0 = __float2bfloat16(a0);
        __nv_bfloat16 h1 = __float2bfloat16(a1);
        __nv_bfloat16 l0 = __float2bfloat16(a0 - __bfloat162float(h0));
        __nv_bfloat16 l1 = __float2bfloat16(a1 - __bfloat162float(h1));
        __nv_bfloat162 vh; vh.x = h0; vh.y = h1;
        __nv_bfloat162 vl; vl.x = l0; vl.y = l1;
        ((__nv_bfloat162*)(g_xh + base))[tx] = vh;
        ((__nv_bfloat162*)(g_xl + base))[tx] = vl;
    }
}

// ---------------- kernel 6: HMMA conv GEMM + BN + ReLU (R5-proven config) ----------------
// CTA 256 thr = 8 warps (2m x 4n), tile 128 co x 256 px; warp tile 64x64.
// 36 stages (9 taps x 4 ci-chunks of 64), 96KB/stage double-buffered.
#define BUF_BYTES 98304
#define NSTAGE    36

__device__ __forceinline__ void stage_tiles(uint32_t sbase, int b, int cog, int pxg,
                                            int s, int tid) {
    int k   = s >> 2;
    int ci0 = (s & 3) << 6;
    int dh  = k / 3 - 1, dw = k % 3 - 1;
    uint32_t buf = sbase + 1024 + (uint32_t)(s & 1) * BUF_BYTES;

    // A: weights [128 co x 64 ci] hi+lo = 2048 x 16B
    size_t wbase = (((size_t)(b * 9 + k) * COUT_ + cog * 128) * CIN_ + ci0) * 2;
    #pragma unroll
    for (int it = 0; it < 8; it++) {
        int c = tid + it * 256;
        int row = c >> 3, c16 = c & 7;
        int hl = row >> 7, r = row & 127;
        uint32_t dst = buf + (uint32_t)hl * 16384 + SWZ128((uint32_t)(r * 128 + c16 * 16));
        const char* src = (const char*)(hl ? g_wl : g_wh) + wbase + (size_t)r * 512 + c16 * 16;
        CP_ASYNC16(dst, src);
    }
    // B: x rows [256 px x 64 ci] hi+lo = 4096 x 16B
    int hbase = 4 * pxg + dh + 1;
    #pragma unroll
    for (int it = 0; it < 16; it++) {
        int c = tid + it * 256;
        int row = c >> 3, c16 = c & 7;
        int hl = row >> 8, p = row & 255;
        int hh = p >> 6, ww = p & 63;
        int pr = (hbase + hh) * PADW + (ww + dw + 1);
        uint32_t dst = buf + 32768 + (uint32_t)hl * 32768 + SWZ128((uint32_t)(p * 128 + c16 * 16));
        const char* src = (const char*)(hl ? g_xl : g_xh)
                          + (((size_t)b * PROWS + pr) * CIN_ + ci0) * 2 + c16 * 16;
        CP_ASYNC16(dst, src);
    }
}

__global__ void __launch_bounds__(256, 1)
conv_kernel(const float* __restrict__ bn_gamma, const float* __restrict__ bn_beta,
            const float* __restrict__ bn_mean,  const float* __restrict__ bn_var,
            float* __restrict__ out) {
    extern __shared__ char smem[];
    uint32_t sbase = smem_u32(smem);
    int b   = blockIdx.z;
    int cog = blockIdx.y;
    int pxg = blockIdx.x;
    int tid = threadIdx.x;
    int wid = tid >> 5;
    int lane = tid & 31;
    int warp_m = wid >> 2;          // 0..1 -> 64 co
    int warp_n = wid & 3;           // 0..3 -> 64 px

    float acc[4][8][4];
    #pragma unroll
    for (int i = 0; i < 4; i++)
        #pragma unroll
        for (int j = 0; j < 8; j++)
            #pragma unroll
            for (int r = 0; r < 4; r++) acc[i][j][r] = 0.f;

    int lA_row = lane & 15;
    int lA_k16 = lane >> 4;
    int lB_row = (lane & 7) + ((lane >> 4) & 1) * 8;
    int lB_k16 = (lane >> 3) & 1;

    stage_tiles(sbase, b, cog, pxg, 0, tid); CP_COMMIT();
    stage_tiles(sbase, b, cog, pxg, 1, tid); CP_COMMIT();

    for (int s = 0; s < NSTAGE; s++) {
        if (s + 1 < NSTAGE) asm volatile("cp.async.wait_group 1;" ::: "memory");
        else                asm volatile("cp.async.wait_group 0;" ::: "memory");
        __syncthreads();

        uint32_t buf = sbase + 1024 + (uint32_t)(s & 1) * BUF_BYTES;
        uint32_t Ah = buf, Al = buf + 16384, Bh = buf + 32768, Bl = buf + 65536;

        #pragma unroll
        for (int kf = 0; kf < 4; kf++) {
            uint32_t ah[16], a2[16], bb[16];
            uint32_t offA[4], offB[4];
            #pragma unroll
            for (int mi = 0; mi < 4; mi++) {
                offA[mi] = SWZ128((uint32_t)((warp_m * 64 + mi * 16 + lA_row) * 128
                                             + kf * 32 + lA_k16 * 16));
                LDSM_X4(&ah[mi * 4], Ah + offA[mi]);
            }
            #pragma unroll
            for (int j = 0; j < 4; j++) {
                offB[j] = SWZ128((uint32_t)((warp_n * 64 + j * 16 + lB_row) * 128
                                            + kf * 32 + lB_k16 * 16));
                LDSM_X4(&bb[j * 4], Bh + offB[j]);
            }
            // pass 1: Ah * Bh
            #pragma unroll
            for (int mi = 0; mi < 4; mi++)
                #pragma unroll
                for (int ni = 0; ni < 8; ni++)
                    MMA_BF16(acc[mi][ni], &ah[mi * 4],
                             bb[(ni >> 1) * 4 + (ni & 1) * 2], bb[(ni >> 1) * 4 + (ni & 1) * 2 + 1]);
            // pass 2: Al * Bh
            #pragma unroll
            for (int mi = 0; mi < 4; mi++) LDSM_X4(&a2[mi * 4], Al + offA[mi]);
            #pragma unroll
            for (int mi = 0; mi < 4; mi++)
                #pragma unroll
                for (int ni = 0; ni < 8; ni++)
                    MMA_BF16(acc[mi][ni], &a2[mi * 4],
                             bb[(ni >> 1) * 4 + (ni & 1) * 2], bb[(ni >> 1) * 4 + (ni & 1) * 2 + 1]);
            // pass 3: Ah * Bl  (Bl reuses bb registers)
            #pragma unroll
            for (int j = 0; j < 4; j++) LDSM_X4(&bb[j * 4], Bl + offB[j]);
            #pragma unroll
            for (int mi = 0; mi < 4; mi++)
                #pragma unroll
                for (int ni = 0; ni < 8; ni++)
                    MMA_BF16(acc[mi][ni], &ah[mi * 4],
                             bb[(ni >> 1) * 4 + (ni & 1) * 2], bb[(ni >> 1) * 4 + (ni & 1) * 2 + 1]);
        }

        __syncthreads();
        if (s + 2 < NSTAGE) { stage_tiles(sbase, b, cog, pxg, s + 2, tid); CP_COMMIT(); }
    }

    // ---------------- epilogue: BN + ReLU + store ----------------
    int co0 = cog * 128 + warp_m * 64;
    float sc[8], sb[8];
    #pragma unroll
    for (int mi = 0; mi < 4; mi++)
        #pragma unroll
        for (int h = 0; h < 2; h++) {
            int co = co0 + mi * 16 + (lane >> 2) + h * 8;
            float s = bn_gamma[co] * rsqrtf(bn_var[co] + BN_EPS_);
            sc[mi * 2 + h] = s;
            sb[mi * 2 + h] = bn_beta[co] - bn_mean[co] * s;
        }

    int pxbase = pxg * 256 + warp_n * 64 + (lane & 3) * 2;
    #pragma unroll
    for (int mi = 0; mi < 4; mi++)
        #pragma unroll
        for (int h = 0; h < 2; h++) {
            int co = co0 + mi * 16 + (lane >> 2) + h * 8;
            float s = sc[mi * 2 + h], bbn = sb[mi * 2 + h];
            float* op = out + ((size_t)(b * COUT_ + co)) * (HW_ * HW_);
            #pragma unroll
            for (int ni = 0; ni < 8; ni++) {
                float2 v;
                v.x = fmaxf(acc[mi][ni][h * 2 + 0] * s + bbn, 0.f);
                v.y = fmaxf(acc[mi][ni][h * 2 + 1] * s + bbn, 0.f);
                *(float2*)(op + pxbase + ni * 8) = v;
            }
        }
}

// ---------------- launcher ----------------
extern "C" void kernel_launch(void* const* d_in, const int* in_sizes, int n_in,
                              void* d_out, int out_size) {
    const float* x        = (const float*)d_in[0];
    const float* weight   = (const float*)d_in[1];
    const float* w_lambda = (const float*)d_in[2];
    const float* w_theta  = (const float*)d_in[3];
    const float* bn_gamma = (const float*)d_in[4];
    const float* bn_beta  = (const float*)d_in[5];
    const float* bn_mean  = (const float*)d_in[6];
    const float* bn_var   = (const float*)d_in[7];
    float* out = (float*)d_out;

    cudaFuncSetAttribute(conv_kernel, cudaFuncAttributeMaxDynamicSharedMemorySize,
                         1024 + 2 * BUF_BYTES);

    pool_kernel<<<B_ * CIN_, 256>>>(x);
    route_kernel<<<1, 64>>>(w_lambda, w_theta);
    rotw_kernel<<<dim3(COUT_, B_), 256>>>(weight);
    border_kernel<<<dim3(260, B_), 128>>>();
    xpose_kernel<<<dim3(128, 4, B_), 256>>>(x);
    conv_kernel<<<dim3(16, 2, B_), 256, 1024 + 2 * BUF_BYTES>>>(
        bn_gamma, bn_beta, bn_mean, bn_var, out);
}

// round 11
// speedup vs baseline: 2.1014x; 1.4638x over previous
#include <cuda_runtime.h>
#include <cuda_fp16.h>
#include <math.h>
#include <stdint.h>

#define B_      16
#define CIN_    256
#define COUT_   256
#define HW_     64
#define KN_     4
#define PI_F    3.14159265358979323846f
#define BN_EPS_ 1e-5f

#define PADW    66
#define PROWS   (PADW * PADW)

// ---------------- scratch (static __device__, zero-initialized) ----------------
__device__ float g_pooled[B_ * CIN_];
__device__ float g_pp[B_ * 128 * CIN_];                    // [b][pxt][ci] partial pools
__device__ float g_T[B_ * 9 * 36];
__device__ __half g_wh[(size_t)B_ * 9 * COUT_ * CIN_];     // [b][k][co][ci] hi
__device__ __half g_wl[(size_t)B_ * 9 * COUT_ * CIN_];     // lo
__device__ __half g_x[(size_t)B_ * PROWS * CIN_];          // [b][padded px][ci] fp16
                                                           // borders stay zero (static init,
                                                           // never written)

// ---------------- helpers ----------------
__device__ __forceinline__ uint32_t smem_u32(const void* p) {
    uint32_t a;
    asm("{ .reg .u64 t; cvta.to.shared.u64 t, %1; cvt.u32.u64 %0, t; }" : "=r"(a) : "l"(p));
    return a;
}
#define SWZ128(o) ((o) ^ (((o) >> 3) & 0x70))

#define CP_ASYNC16(dst, src) asm volatile("cp.async.cg.shared.global [%0], [%1], 16;" :: "r"(dst), "l"(src) : "memory")
#define CP_COMMIT()          asm volatile("cp.async.commit_group;" ::: "memory")

#define LDSM_X4(r, a)                                                                     \
    asm volatile("ldmatrix.sync.aligned.m8n8.x4.shared.b16 {%0,%1,%2,%3}, [%4];"          \
                 : "=r"((r)[0]), "=r"((r)[1]), "=r"((r)[2]), "=r"((r)[3]) : "r"(a))

#define MMA_F16(d, a, b0, b1)                                                             \
    asm volatile("mma.sync.aligned.m16n8k16.row.col.f32.f16.f16.f32 "                     \
                 "{%0,%1,%2,%3},{%4,%5,%6,%7},{%8,%9},{%0,%1,%2,%3};"                     \
                 : "+f"((d)[0]), "+f"((d)[1]), "+f"((d)[2]), "+f"((d)[3])                 \
                 : "r"((a)[0]), "r"((a)[1]), "r"((a)[2]), "r"((a)[3]), "r"(b0), "r"(b1))

// ---------------- kernel 1: transpose+convert x -> g_x fp16, + partial GAP ----------------
__global__ void xpose_kernel(const float* __restrict__ x) {
    int b   = blockIdx.z;
    int ci0 = blockIdx.y * 64;
    int pxt = blockIdx.x;
    int px0 = pxt * 32;
    __shared__ float t[64][33];
    int tid = threadIdx.x;
    int tx = tid & 31, ty = tid >> 5;

    const float* xb = x + ((size_t)(b * CIN_ + ci0)) * (HW_ * HW_) + px0;
    #pragma unroll
    for (int i = 0; i < 8; i++)
        t[ty + 8 * i][tx] = xb[(size_t)(ty + 8 * i) * (HW_ * HW_) + tx];
    __syncthreads();

    // transposed fp16 writes (interior pixels only)
    #pragma unroll
    for (int i = 0; i < 4; i++) {
        int px = px0 + ty + 8 * i;
        int h = px >> 6, w = px & 63;
        int pr = (h + 1) * PADW + (w + 1);
        size_t base = ((size_t)b * PROWS + pr) * CIN_ + ci0;
        __half2 v;
        v.x = __float2half(t[2 * tx][ty + 8 * i]);
        v.y = __float2half(t[2 * tx + 1][ty + 8 * i]);
        ((__half2*)(g_x + base))[tx] = v;
    }

    // partial global-average-pool: sum 32 px for each of 64 ci
    int ci = tid >> 2;          // 0..63
    int q  = tid & 3;           // quarter of the 32 px
    float s = 0.f;
    #pragma unroll
    for (int j = 0; j < 8; j++) s += t[ci][q * 8 + j];
    s += __shfl_down_sync(0xffffffffu, s, 1);
    s += __shfl_down_sync(0xffffffffu, s, 2);
    if (q == 0) g_pp[((size_t)b * 128 + pxt) * CIN_ + ci0 + ci] = s;
}

// ---------------- kernel 2: reduce partial pools ----------------
__global__ void pool_reduce_kernel() {
    int b  = blockIdx.x;
    int ci = threadIdx.x;
    float s = 0.f;
    for (int pxt = 0; pxt < 128; pxt++)
        s += g_pp[((size_t)b * 128 + pxt) * CIN_ + ci];
    g_pooled[b * CIN_ + ci] = s * (1.f / (HW_ * HW_));
}

// ---------------- kernel 3: routing heads + rotation matrices -> g_T ----------------
__global__ void route_kernel(const float* __restrict__ wl, const float* __restrict__ wt) {
    int t = threadIdx.x;
    if (t >= B_ * KN_) return;
    int b = t >> 2, n = t & 3;
    const float* p = g_pooled + b * CIN_;
    float dl = 0.f, dt = 0.f;
    for (int c = 0; c < CIN_; c++) {
        float pc = p[c];
        dl += pc * wl[c * KN_ + n];
        dt += pc * wt[c * KN_ + n];
    }
    float lam = 1.f / (1.f + expf(-dl));
    float th  = (dt / (1.f + fabsf(dt))) * PI_F;

    float xc = cosf(th), ys = sinf(th);
    float a = xc - ys, bxy = xc * ys, cc = xc + ys;

    float R[81];
    #pragma unroll
    for (int i = 0; i < 81; i++) R[i] = 0.f;

    if (th >= 0.f) {
        R[0]  = a;          R[1]  = 1.f - a;
        R[10] = xc - bxy;   R[11] = bxy;        R[13] = 1.f - cc + bxy; R[14] = ys - bxy;
        R[20] = a;          R[23] = 1.f - a;
        R[27] = bxy;        R[28] = ys - bxy;   R[30] = xc - bxy;       R[31] = 1.f - cc + bxy;
        R[40] = 1.f;
        R[49] = 1.f - cc + bxy; R[50] = xc - bxy; R[52] = ys - bxy;     R[53] = bxy;
        R[57] = 1.f - a;    R[60] = a;
        R[66] = ys - bxy;   R[67] = 1.f - cc + bxy; R[69] = bxy;        R[70] = xc - bxy;
        R[79] = 1.f - a;    R[80] = a;
    } else {
        R[0]  = cc;         R[3]  = 1.f - cc;
        R[9]  = -bxy;       R[10] = xc + bxy;   R[12] = bxy - ys;       R[13] = 1.f - a - bxy;
        R[19] = 1.f - cc;   R[20] = cc;
        R[30] = xc + bxy;   R[31] = 1.f - a - bxy; R[33] = -bxy;        R[34] = bxy - ys;
        R[40] = 1.f;
        R[46] = bxy - ys;   R[47] = -bxy;       R[49] = 1.f - a - bxy;  R[50] = xc + bxy;
        R[60] = cc;         R[61] = 1.f - cc;
        R[67] = 1.f - a - bxy; R[68] = bxy - ys; R[70] = xc + bxy;      R[71] = -bxy;
        R[77] = 1.f - cc;   R[80] = cc;
    }

    #pragma unroll
    for (int pp = 0; pp < 9; pp++)
        #pragma unroll
        for (int q = 0; q < 9; q++)
            g_T[b * 324 + pp * 36 + n * 9 + q] = lam * R[pp * 9 + q];
}

// ---------------- kernel 4: rotated weights -> fp16 hi/lo [b][k][co][ci] ----------------
// grid (256 co, 4 b-groups); weight slice read once per block, loop over 4 b.
__global__ void rotw_kernel(const float* __restrict__ weight) {
    int co = blockIdx.x;
    int bg = blockIdx.y;                // 4 batches per block
    int ci = threadIdx.x;
    int tid = threadIdx.x;

    __shared__ float ws[KN_ * CIN_ * 9];    // 36 KB
    __shared__ float Ts[4 * 324];           // 5.2 KB

    #pragma unroll
    for (int n = 0; n < KN_; n++) {
        const float* wp = weight + ((size_t)(n * COUT_ + co)) * CIN_ * 9;
        for (int i = tid; i < CIN_ * 9; i += 256) ws[n * CIN_ * 9 + i] = wp[i];
    }
    for (int i = tid; i < 4 * 324; i += 256) Ts[i] = g_T[bg * 4 * 324 + i];
    __syncthreads();

    float wv[36];
    #pragma unroll
    for (int n = 0; n < KN_; n++)
        #pragma unroll
        for (int q = 0; q < 9; q++) wv[n * 9 + q] = ws[n * CIN_ * 9 + ci * 9 + q];

    #pragma unroll
    for (int bi = 0; bi < 4; bi++) {
        int b = bg * 4 + bi;
        #pragma unroll
        for (int p = 0; p < 9; p++) {
            float s = 0.f;
            #pragma unroll
            for (int m = 0; m < 36; m++) s += Ts[bi * 324 + p * 36 + m] * wv[m];
            __half hi = __float2half(s);
            __half lo = __float2half(s - __half2float(hi));
            size_t o = ((size_t)(b * 9 + p) * COUT_ + co) * CIN_ + ci;
            g_wh[o] = hi;
            g_wl[o] = lo;
        }
    }
}

// ---------------- kernel 5: HMMA fp16 2-pass conv GEMM + BN + ReLU ----------------
// CTA 256 thr = 8 warps (2m x 4n), tile 128 co x 256 px; warp tile 64x64.
// 36 stages (9 taps x 4 ci-chunks of 64): A hi 16K | A lo 16K | B 32K = 64KB, 3-ring.
#define BUF_BYTES 65536
#define NSTAGE    36

__device__ __forceinline__ void stage_tiles(uint32_t buf, int b, int cog, int pxg,
                                            int s, int tid) {
    int k   = s >> 2;
    int ci0 = (s & 3) << 6;
    int dh  = k / 3 - 1, dw = k % 3 - 1;

    // A: weights [128 co x 64 ci] hi+lo = 2048 x 16B
    size_t wbase = (((size_t)(b * 9 + k) * COUT_ + cog * 128) * CIN_ + ci0) * 2;
    #pragma unroll
    for (int it = 0; it < 8; it++) {
        int c = tid + it * 256;
        int row = c >> 3, c16 = c & 7;
        int hl = row >> 7, r = row & 127;
        uint32_t dst = buf + (uint32_t)hl * 16384 + SWZ128((uint32_t)(r * 128 + c16 * 16));
        const char* src = (const char*)(hl ? g_wl : g_wh) + wbase + (size_t)r * 512 + c16 * 16;
        CP_ASYNC16(dst, src);
    }
    // B: x rows [256 px x 64 ci] fp16 = 2048 x 16B
    int hbase = 4 * pxg + dh + 1;
    #pragma unroll
    for (int it = 0; it < 8; it++) {
        int c = tid + it * 256;
        int row = c >> 3, c16 = c & 7;
        int p = row;
        int hh = p >> 6, ww = p & 63;
        int pr = (hbase + hh) * PADW + (ww + dw + 1);
        uint32_t dst = buf + 32768 + SWZ128((uint32_t)(p * 128 + c16 * 16));
        const char* src = (const char*)g_x
                          + (((size_t)b * PROWS + pr) * CIN_ + ci0) * 2 + c16 * 16;
        CP_ASYNC16(dst, src);
    }
}

__global__ void __launch_bounds__(256, 1)
conv_kernel(const float* __restrict__ bn_gamma, const float* __restrict__ bn_beta,
            const float* __restrict__ bn_mean,  const float* __restrict__ bn_var,
            float* __restrict__ out) {
    extern __shared__ char smem[];
    uint32_t sbase = smem_u32(smem);
    int b   = blockIdx.z;
    int cog = blockIdx.y;
    int pxg = blockIdx.x;
    int tid = threadIdx.x;
    int wid = tid >> 5;
    int lane = tid & 31;
    int warp_m = wid >> 2;          // 0..1 -> 64 co
    int warp_n = wid & 3;           // 0..3 -> 64 px

    float acc[4][8][4];
    #pragma unroll
    for (int i = 0; i < 4; i++)
        #pragma unroll
        for (int j = 0; j < 8; j++)
            #pragma unroll
            for (int r = 0; r < 4; r++) acc[i][j][r] = 0.f;

    int lA_row = lane & 15;
    int lA_k16 = lane >> 4;
    int lB_row = (lane & 7) + ((lane >> 4) & 1) * 8;
    int lB_k16 = (lane >> 3) & 1;

    uint32_t bufs[3] = { sbase + 1024, sbase + 1024 + BUF_BYTES, sbase + 1024 + 2 * BUF_BYTES };

    stage_tiles(bufs[0], b, cog, pxg, 0, tid); CP_COMMIT();
    stage_tiles(bufs[1], b, cog, pxg, 1, tid); CP_COMMIT();
    stage_tiles(bufs[2], b, cog, pxg, 2, tid); CP_COMMIT();

    int idx = 0;
    for (int s = 0; s < NSTAGE; s++) {
        if (s + 3 < NSTAGE)      asm volatile("cp.async.wait_group 2;" ::: "memory");
        else if (s + 2 < NSTAGE) asm volatile("cp.async.wait_group 1;" ::: "memory");
        else                     asm volatile("cp.async.wait_group 0;" ::: "memory");
        __syncthreads();

        uint32_t buf = bufs[idx];
        uint32_t Ah = buf, Al = buf + 16384, Bx = buf + 32768;

        #pragma unroll
        for (int kf = 0; kf < 4; kf++) {
            uint32_t ah[16], bb[16];
            uint32_t offA[4], offB[4];
            #pragma unroll
            for (int mi = 0; mi < 4; mi++) {
                offA[mi] = SWZ128((uint32_t)((warp_m * 64 + mi * 16 + lA_row) * 128
                                             + kf * 32 + lA_k16 * 16));
                LDSM_X4(&ah[mi * 4], Ah + offA[mi]);
            }
            #pragma unroll
            for (int j = 0; j < 4; j++) {
                offB[j] = SWZ128((uint32_t)((warp_n * 64 + j * 16 + lB_row) * 128
                                            + kf * 32 + lB_k16 * 16));
                LDSM_X4(&bb[j * 4], Bx + offB[j]);
            }
            // pass 1: Ah * B
            #pragma unroll
            for (int mi = 0; mi < 4; mi++)
                #pragma unroll
                for (int ni = 0; ni < 8; ni++)
                    MMA_F16(acc[mi][ni], &ah[mi * 4],
                            bb[(ni >> 1) * 4 + (ni & 1) * 2], bb[(ni >> 1) * 4 + (ni & 1) * 2 + 1]);
            // pass 2: Al * B  (Al reuses ah registers)
            #pragma unroll
            for (int mi = 0; mi < 4; mi++) LDSM_X4(&ah[mi * 4], Al + offA[mi]);
            #pragma unroll
            for (int mi = 0; mi < 4; mi++)
                #pragma unroll
                for (int ni = 0; ni < 8; ni++)
                    MMA_F16(acc[mi][ni], &ah[mi * 4],
                            bb[(ni >> 1) * 4 + (ni & 1) * 2], bb[(ni >> 1) * 4 + (ni & 1) * 2 + 1]);
        }

        __syncthreads();
        if (s + 3 < NSTAGE) { stage_tiles(bufs[idx], b, cog, pxg, s + 3, tid); CP_COMMIT(); }
        idx = (idx == 2) ? 0 : idx + 1;
    }

    // ---------------- epilogue: BN + ReLU + store ----------------
    int co0 = cog * 128 + warp_m * 64;
    float sc[8], sb[8];
    #pragma unroll
    for (int mi = 0; mi < 4; mi++)
        #pragma unroll
        for (int h = 0; h < 2; h++) {
            int co = co0 + mi * 16 + (lane >> 2) + h * 8;
            float s = bn_gamma[co] * rsqrtf(bn_var[co] + BN_EPS_);
            sc[mi * 2 + h] = s;
            sb[mi * 2 + h] = bn_beta[co] - bn_mean[co] * s;
        }

    int pxbase = pxg * 256 + warp_n * 64 + (lane & 3) * 2;
    #pragma unroll
    for (int mi = 0; mi < 4; mi++)
        #pragma unroll
        for (int h = 0; h < 2; h++) {
            int co = co0 + mi * 16 + (lane >> 2) + h * 8;
            float s = sc[mi * 2 + h], bbn = sb[mi * 2 + h];
            float* op = out + ((size_t)(b * COUT_ + co)) * (HW_ * HW_);
            #pragma unroll
            for (int ni = 0; ni < 8; ni++) {
                float2 v;
                v.x = fmaxf(acc[mi][ni][h * 2 + 0] * s + bbn, 0.f);
                v.y = fmaxf(acc[mi][ni][h * 2 + 1] * s + bbn, 0.f);
                *(float2*)(op + pxbase + ni * 8) = v;
            }
        }
}

// ---------------- launcher ----------------
extern "C" void kernel_launch(void* const* d_in, const int* in_sizes, int n_in,
                              void* d_out, int out_size) {
    const float* x        = (const float*)d_in[0];
    const float* weight   = (const float*)d_in[1];
    const float* w_lambda = (const float*)d_in[2];
    const float* w_theta  = (const float*)d_in[3];
    const float* bn_gamma = (const float*)d_in[4];
    const float* bn_beta  = (const float*)d_in[5];
    const float* bn_mean  = (const float*)d_in[6];
    const float* bn_var   = (const float*)d_in[7];
    float* out = (float*)d_out;

    cudaFuncSetAttribute(conv_kernel, cudaFuncAttributeMaxDynamicSharedMemorySize,
                         1024 + 3 * BUF_BYTES);

    xpose_kernel<<<dim3(128, 4, B_), 256>>>(x);
    pool_reduce_kernel<<<B_, 256>>>();
    route_kernel<<<1, 64>>>(w_lambda, w_theta);
    rotw_kernel<<<dim3(COUT_, 4), 256>>>(weight);
    conv_kernel<<<dim3(16, 2, B_), 256, 1024 + 3 * BUF_BYTES>>>(
        bn_gamma, bn_beta, bn_mean, bn_var, out);
}

// round 15
// speedup vs baseline: 3.1049x; 1.4775x over previous
#include <cuda_runtime.h>
#include <cuda_fp16.h>
#include <math.h>
#include <stdint.h>

#define B_      16
#define CIN_    256
#define COUT_   256
#define HW_     64
#define KN_     4
#define PI_F    3.14159265358979323846f
#define BN_EPS_ 1e-5f

#define PADW    66
#define PROWS   (PADW * PADW)

// ---------------- scratch (static __device__, zero-initialized) ----------------
__device__ float g_pooled[B_ * CIN_];
__device__ float g_pp[B_ * 128 * CIN_];                    // [b][pxt][ci] partial pools
__device__ float g_T[B_ * 9 * 36];
__device__ __half g_w[(size_t)B_ * 9 * COUT_ * CIN_];      // [b][k][co][ci] fp16
__device__ __half g_x[(size_t)B_ * PROWS * CIN_];          // [b][padded px][ci] fp16
                                                           // borders stay zero (static init)

// ---------------- helpers ----------------
__device__ __forceinline__ uint32_t smem_u32(const void* p) {
    uint32_t a;
    asm("{ .reg .u64 t; cvta.to.shared.u64 t, %1; cvt.u32.u64 %0, t; }" : "=r"(a) : "l"(p));
    return a;
}
#define SWZ128(o) ((o) ^ (((o) >> 3) & 0x70))

#define CP_ASYNC16(dst, src) asm volatile("cp.async.cg.shared.global [%0], [%1], 16;" :: "r"(dst), "l"(src) : "memory")
#define CP_COMMIT()          asm volatile("cp.async.commit_group;" ::: "memory")

#define LDSM_X4(r, a)                                                                     \
    asm volatile("ldmatrix.sync.aligned.m8n8.x4.shared.b16 {%0,%1,%2,%3}, [%4];"          \
                 : "=r"((r)[0]), "=r"((r)[1]), "=r"((r)[2]), "=r"((r)[3]) : "r"(a))

#define MMA_F16(d, a, b0, b1)                                                             \
    asm volatile("mma.sync.aligned.m16n8k16.row.col.f32.f16.f16.f32 "                     \
                 "{%0,%1,%2,%3},{%4,%5,%6,%7},{%8,%9},{%0,%1,%2,%3};"                     \
                 : "+f"((d)[0]), "+f"((d)[1]), "+f"((d)[2]), "+f"((d)[3])                 \
                 : "r"((a)[0]), "r"((a)[1]), "r"((a)[2]), "r"((a)[3]), "r"(b0), "r"(b1))

// ---------------- kernel 1: transpose+convert x -> g_x fp16, + partial GAP ----------------
__global__ void xpose_kernel(const float* __restrict__ x) {
    int b   = blockIdx.z;
    int ci0 = blockIdx.y * 64;
    int pxt = blockIdx.x;
    int px0 = pxt * 32;
    __shared__ float t[64][33];
    int tid = threadIdx.x;
    int tx = tid & 31, ty = tid >> 5;

    const float* xb = x + ((size_t)(b * CIN_ + ci0)) * (HW_ * HW_) + px0;
    #pragma unroll
    for (int i = 0; i < 8; i++)
        t[ty + 8 * i][tx] = xb[(size_t)(ty + 8 * i) * (HW_ * HW_) + tx];
    __syncthreads();

    // transposed fp16 writes (interior pixels only)
    #pragma unroll
    for (int i = 0; i < 4; i++) {
        int px = px0 + ty + 8 * i;
        int h = px >> 6, w = px & 63;
        int pr = (h + 1) * PADW + (w + 1);
        size_t base = ((size_t)b * PROWS + pr) * CIN_ + ci0;
        __half2 v;
        v.x = __float2half(t[2 * tx][ty + 8 * i]);
        v.y = __float2half(t[2 * tx + 1][ty + 8 * i]);
        ((__half2*)(g_x + base))[tx] = v;
    }

    // partial global-average-pool: sum 32 px for each of 64 ci
    int ci = tid >> 2;
    int q  = tid & 3;
    float s = 0.f;
    #pragma unroll
    for (int j = 0; j < 8; j++) s += t[ci][q * 8 + j];
    s += __shfl_down_sync(0xffffffffu, s, 1);
    s += __shfl_down_sync(0xffffffffu, s, 2);
    if (q == 0) g_pp[((size_t)b * 128 + pxt) * CIN_ + ci0 + ci] = s;
}

// ---------------- kernel 2: reduce partial pools ----------------
__global__ void pool_reduce_kernel() {
    int b  = blockIdx.x;
    int ci = threadIdx.x;
    float s = 0.f;
    for (int pxt = 0; pxt < 128; pxt++)
        s += g_pp[((size_t)b * 128 + pxt) * CIN_ + ci];
    g_pooled[b * CIN_ + ci] = s * (1.f / (HW_ * HW_));
}

// ---------------- kernel 3: routing heads + rotation matrices -> g_T ----------------
__global__ void route_kernel(const float* __restrict__ wl, const float* __restrict__ wt) {
    int t = threadIdx.x;
    if (t >= B_ * KN_) return;
    int b = t >> 2, n = t & 3;
    const float* p = g_pooled + b * CIN_;
    float dl = 0.f, dt = 0.f;
    for (int c = 0; c < CIN_; c++) {
        float pc = p[c];
        dl += pc * wl[c * KN_ + n];
        dt += pc * wt[c * KN_ + n];
    }
    float lam = 1.f / (1.f + expf(-dl));
    float th  = (dt / (1.f + fabsf(dt))) * PI_F;

    float xc = cosf(th), ys = sinf(th);
    float a = xc - ys, bxy = xc * ys, cc = xc + ys;

    float R[81];
    #pragma unroll
    for (int i = 0; i < 81; i++) R[i] = 0.f;

    if (th >= 0.f) {
        R[0]  = a;          R[1]  = 1.f - a;
        R[10] = xc - bxy;   R[11] = bxy;        R[13] = 1.f - cc + bxy; R[14] = ys - bxy;
        R[20] = a;          R[23] = 1.f - a;
        R[27] = bxy;        R[28] = ys - bxy;   R[30] = xc - bxy;       R[31] = 1.f - cc + bxy;
        R[40] = 1.f;
        R[49] = 1.f - cc + bxy; R[50] = xc - bxy; R[52] = ys - bxy;     R[53] = bxy;
        R[57] = 1.f - a;    R[60] = a;
        R[66] = ys - bxy;   R[67] = 1.f - cc + bxy; R[69] = bxy;        R[70] = xc - bxy;
        R[79] = 1.f - a;    R[80] = a;
    } else {
        R[0]  = cc;         R[3]  = 1.f - cc;
        R[9]  = -bxy;       R[10] = xc + bxy;   R[12] = bxy - ys;       R[13] = 1.f - a - bxy;
        R[19] = 1.f - cc;   R[20] = cc;
        R[30] = xc + bxy;   R[31] = 1.f - a - bxy; R[33] = -bxy;        R[34] = bxy - ys;
        R[40] = 1.f;
        R[46] = bxy - ys;   R[47] = -bxy;       R[49] = 1.f - a - bxy;  R[50] = xc + bxy;
        R[60] = cc;         R[61] = 1.f - cc;
        R[67] = 1.f - a - bxy; R[68] = bxy - ys; R[70] = xc + bxy;      R[71] = -bxy;
        R[77] = 1.f - cc;   R[80] = cc;
    }

    #pragma unroll
    for (int pp = 0; pp < 9; pp++)
        #pragma unroll
        for (int q = 0; q < 9; q++)
            g_T[b * 324 + pp * 36 + n * 9 + q] = lam * R[pp * 9 + q];
}

// ---------------- kernel 4: rotated weights -> fp16 [b][k][co][ci] ----------------
__global__ void rotw_kernel(const float* __restrict__ weight) {
    int co = blockIdx.x;
    int bg = blockIdx.y;                // 4 batches per block
    int ci = threadIdx.x;
    int tid = threadIdx.x;

    __shared__ float ws[KN_ * CIN_ * 9];    // 36 KB
    __shared__ float Ts[4 * 324];           // 5.2 KB

    #pragma unroll
    for (int n = 0; n < KN_; n++) {
        const float* wp = weight + ((size_t)(n * COUT_ + co)) * CIN_ * 9;
        for (int i = tid; i < CIN_ * 9; i += 256) ws[n * CIN_ * 9 + i] = wp[i];
    }
    for (int i = tid; i < 4 * 324; i += 256) Ts[i] = g_T[bg * 4 * 324 + i];
    __syncthreads();

    float wv[36];
    #pragma unroll
    for (int n = 0; n < KN_; n++)
        #pragma unroll
        for (int q = 0; q < 9; q++) wv[n * 9 + q] = ws[n * CIN_ * 9 + ci * 9 + q];

    #pragma unroll
    for (int bi = 0; bi < 4; bi++) {
        int b = bg * 4 + bi;
        #pragma unroll
        for (int p = 0; p < 9; p++) {
            float s = 0.f;
            #pragma unroll
            for (int m = 0; m < 36; m++) s += Ts[bi * 324 + p * 36 + m] * wv[m];
            size_t o = ((size_t)(b * 9 + p) * COUT_ + co) * CIN_ + ci;
            g_w[o] = __float2half(s);
        }
    }
}

// ---------------- kernel 5: HMMA fp16 single-pass conv GEMM + BN + ReLU ----------------
// CTA 256 thr = 8 warps (2m x 4n), tile 128 co x 256 px; warp tile 64x64.
// 36 stages (9 taps x 4 ci-chunks of 64): A 16K | B 32K = 48KB, 4-deep ring.
#define BUF_BYTES 49152
#define NSTAGE    36

__device__ __forceinline__ void stage_tiles(uint32_t buf, int b, int cog, int pxg,
                                            int s, int tid) {
    int k   = s >> 2;
    int ci0 = (s & 3) << 6;
    int dh  = k / 3 - 1, dw = k % 3 - 1;

    // A: weights [128 co x 64 ci] = 1024 x 16B
    size_t wbase = (((size_t)(b * 9 + k) * COUT_ + cog * 128) * CIN_ + ci0) * 2;
    #pragma unroll
    for (int it = 0; it < 4; it++) {
        int c = tid + it * 256;
        int row = c >> 3, c16 = c & 7;
        uint32_t dst = buf + SWZ128((uint32_t)(row * 128 + c16 * 16));
        const char* src = (const char*)g_w + wbase + (size_t)row * 512 + c16 * 16;
        CP_ASYNC16(dst, src);
    }
    // B: x rows [256 px x 64 ci] = 2048 x 16B
    int hbase = 4 * pxg + dh + 1;
    #pragma unroll
    for (int it = 0; it < 8; it++) {
        int c = tid + it * 256;
        int row = c >> 3, c16 = c & 7;
        int hh = row >> 6, ww = row & 63;
        int pr = (hbase + hh) * PADW + (ww + dw + 1);
        uint32_t dst = buf + 16384 + SWZ128((uint32_t)(row * 128 + c16 * 16));
        const char* src = (const char*)g_x
                          + (((size_t)b * PROWS + pr) * CIN_ + ci0) * 2 + c16 * 16;
        CP_ASYNC16(dst, src);
    }
}

__global__ void __launch_bounds__(256, 1)
conv_kernel(const float* __restrict__ bn_gamma, const float* __restrict__ bn_beta,
            const float* __restrict__ bn_mean,  const float* __restrict__ bn_var,
            float* __restrict__ out) {
    extern __shared__ char smem[];
    uint32_t sbase = smem_u32(smem);
    int b   = blockIdx.z;
    int cog = blockIdx.y;
    int pxg = blockIdx.x;
    int tid = threadIdx.x;
    int wid = tid >> 5;
    int lane = tid & 31;
    int warp_m = wid >> 2;          // 0..1 -> 64 co
    int warp_n = wid & 3;           // 0..3 -> 64 px

    float acc[4][8][4];
    #pragma unroll
    for (int i = 0; i < 4; i++)
        #pragma unroll
        for (int j = 0; j < 8; j++)
            #pragma unroll
            for (int r = 0; r < 4; r++) acc[i][j][r] = 0.f;

    int lA_row = lane & 15;
    int lA_k16 = lane >> 4;
    int lB_row = (lane & 7) + ((lane >> 4) & 1) * 8;
    int lB_k16 = (lane >> 3) & 1;

    uint32_t bufs[4] = { sbase + 1024, sbase + 1024 + BUF_BYTES,
                         sbase + 1024 + 2 * BUF_BYTES, sbase + 1024 + 3 * BUF_BYTES };

    stage_tiles(bufs[0], b, cog, pxg, 0, tid); CP_COMMIT();
    stage_tiles(bufs[1], b, cog, pxg, 1, tid); CP_COMMIT();
    stage_tiles(bufs[2], b, cog, pxg, 2, tid); CP_COMMIT();
    stage_tiles(bufs[3], b, cog, pxg, 3, tid); CP_COMMIT();

    int idx = 0;
    for (int s = 0; s < NSTAGE; s++) {
        if (s + 4 < NSTAGE)      asm volatile("cp.async.wait_group 3;" ::: "memory");
        else if (s + 3 < NSTAGE) asm volatile("cp.async.wait_group 2;" ::: "memory");
        else if (s + 2 < NSTAGE) asm volatile("cp.async.wait_group 1;" ::: "memory");
        else                     asm volatile("cp.async.wait_group 0;" ::: "memory");
        __syncthreads();

        uint32_t buf = bufs[idx];
        uint32_t Ax = buf, Bx = buf + 16384;

        #pragma unroll
        for (int kf = 0; kf < 4; kf++) {
            uint32_t ah[16], bb[16];
            #pragma unroll
            for (int mi = 0; mi < 4; mi++) {
                uint32_t offA = SWZ128((uint32_t)((warp_m * 64 + mi * 16 + lA_row) * 128
                                                  + kf * 32 + lA_k16 * 16));
                LDSM_X4(&ah[mi * 4], Ax + offA);
            }
            #pragma unroll
            for (int j = 0; j < 4; j++) {
                uint32_t offB = SWZ128((uint32_t)((warp_n * 64 + j * 16 + lB_row) * 128
                                                  + kf * 32 + lB_k16 * 16));
                LDSM_X4(&bb[j * 4], Bx + offB);
            }
            #pragma unroll
            for (int mi = 0; mi < 4; mi++)
                #pragma unroll
                for (int ni = 0; ni < 8; ni++)
                    MMA_F16(acc[mi][ni], &ah[mi * 4],
                            bb[(ni >> 1) * 4 + (ni & 1) * 2], bb[(ni >> 1) * 4 + (ni & 1) * 2 + 1]);
        }

        __syncthreads();
        if (s + 4 < NSTAGE) { stage_tiles(bufs[idx], b, cog, pxg, s + 4, tid); CP_COMMIT(); }
        idx = (idx + 1) & 3;
    }

    // ---------------- epilogue: BN + ReLU + store ----------------
    int co0 = cog * 128 + warp_m * 64;
    float sc[8], sb[8];
    #pragma unroll
    for (int mi = 0; mi < 4; mi++)
        #pragma unroll
        for (int h = 0; h < 2; h++) {
            int co = co0 + mi * 16 + (lane >> 2) + h * 8;
            float s = bn_gamma[co] * rsqrtf(bn_var[co] + BN_EPS_);
            sc[mi * 2 + h] = s;
            sb[mi * 2 + h] = bn_beta[co] - bn_mean[co] * s;
        }

    int pxbase = pxg * 256 + warp_n * 64 + (lane & 3) * 2;
    #pragma unroll
    for (int mi = 0; mi < 4; mi++)
        #pragma unroll
        for (int h = 0; h < 2; h++) {
            int co = co0 + mi * 16 + (lane >> 2) + h * 8;
            float s = sc[mi * 2 + h], bbn = sb[mi * 2 + h];
            float* op = out + ((size_t)(b * COUT_ + co)) * (HW_ * HW_);
            #pragma unroll
            for (int ni = 0; ni < 8; ni++) {
                float2 v;
                v.x = fmaxf(acc[mi][ni][h * 2 + 0] * s + bbn, 0.f);
                v.y = fmaxf(acc[mi][ni][h * 2 + 1] * s + bbn, 0.f);
                *(float2*)(op + pxbase + ni * 8) = v;
            }
        }
}

// ---------------- launcher ----------------
extern "C" void kernel_launch(void* const* d_in, const int* in_sizes, int n_in,
                              void* d_out, int out_size) {
    const float* x        = (const float*)d_in[0];
    const float* weight   = (const float*)d_in[1];
    const float* w_lambda = (const float*)d_in[2];
    const float* w_theta  = (const float*)d_in[3];
    const float* bn_gamma = (const float*)d_in[4];
    const float* bn_beta  = (const float*)d_in[5];
    const float* bn_mean  = (const float*)d_in[6];
    const float* bn_var   = (const float*)d_in[7];
    float* out = (float*)d_out;

    cudaFuncSetAttribute(conv_kernel, cudaFuncAttributeMaxDynamicSharedMemorySize,
                         1024 + 4 * BUF_BYTES);

    xpose_kernel<<<dim3(128, 4, B_), 256>>>(x);
    pool_reduce_kernel<<<B_, 256>>>();
    route_kernel<<<1, 64>>>(w_lambda, w_theta);
    rotw_kernel<<<dim3(COUT_, 4), 256>>>(weight);
    conv_kernel<<<dim3(16, 2, B_), 256, 1024 + 4 * BUF_BYTES>>>(
        bn_gamma, bn_beta, bn_mean, bn_var, out);
}